// round 11
// baseline (speedup 1.0000x reference)
#include <cuda_runtime.h>
#include <cuda_fp16.h>
#include <cstdint>

#define NN      500000
#define NE      8000000
#define NG      16384
#define INF     74
#define HID     64
#define CH      128
#define NB      489          // ceil(NN/1024) for the scan
#define NT      (NN / 32)    // 15625 row tiles
#define GRID_L0 592
#define GRID_64 740

// ---------------- scratch (device globals; no allocation) ----------------
__device__ __half g_Ph [(size_t)NN * HID];  // h @ gW, fp16 (L2-pinned)
__device__ float  g_R  [(size_t)NN * HID];  // relu(h @ rW + rb), streaming
__device__ float  g_H  [(size_t)NN * HID];  // layer output H, streaming
__device__ float  g_GF [(size_t)NG * HID];  // pooled graph features

// CSR build scratch
__device__ int g_cnt [NN];
__device__ int g_off [NN + 1];
__device__ int g_cur [NN];
__device__ int g_bsum [512];
__device__ int g_esrc[NE];                  // src ids grouped by dst (L2-pinned)

// degree-sort scratch
__device__ int g_dh  [256];                 // degree histogram (clamped to 255)
__device__ int g_dcur[256];                 // running bin offsets
__device__ int g_perm[NN];                  // nodes sorted by degree

// ---------------- side stream + events + smem opt-in (once; no device mem) ----------------
__global__ void __launch_bounds__(256) gemm_l0(const float*, const float*, const float*, const float*);
struct AuxRes {
    cudaStream_t s;
    cudaEvent_t eFork, eJoin;
    AuxRes() {
        cudaStreamCreate(&s);
        cudaEventCreateWithFlags(&eFork, cudaEventDisableTiming);
        cudaEventCreateWithFlags(&eJoin, cudaEventDisableTiming);
        cudaFuncSetAttribute(gemm_l0, cudaFuncAttributeMaxDynamicSharedMemorySize, 56 * 1024);
    }
};
static AuxRes g_aux;

// ---------------- helpers ----------------
__device__ __forceinline__ void red4(float* p, float4 v) {
    asm volatile("red.global.add.v4.f32 [%0], {%1,%2,%3,%4};"
                 :: "l"(p), "f"(v.x), "f"(v.y), "f"(v.z), "f"(v.w)
                 : "memory");
}

__device__ __forceinline__ unsigned long long mk_pol_last() {
    unsigned long long p;
    asm("createpolicy.fractional.L2::evict_last.b64 %0, 1.0;" : "=l"(p));
    return p;
}
__device__ __forceinline__ uint2 ld_el_u2(const uint2* a, unsigned long long pol) {
    uint2 r;
    asm("ld.global.nc.L2::cache_hint.v2.u32 {%0,%1}, [%2], %3;"
        : "=r"(r.x), "=r"(r.y) : "l"(a), "l"(pol));
    return r;
}
__device__ __forceinline__ int ld_el_s32(const int* a, unsigned long long pol) {
    int r;
    asm("ld.global.nc.L2::cache_hint.b32 %0, [%1], %2;" : "=r"(r) : "l"(a), "l"(pol));
    return r;
}
__device__ __forceinline__ void st_el_u32(unsigned* a, unsigned v, unsigned long long pol) {
    asm volatile("st.global.L2::cache_hint.b32 [%0], %1, %2;" :: "l"(a), "r"(v), "l"(pol) : "memory");
}

__device__ __forceinline__ unsigned tf32r(float x) {
    unsigned u;
    asm("cvt.rna.tf32.f32 %0, %1;" : "=r"(u) : "f"(x));
    return u;
}

__device__ __forceinline__ void mma_tf32(float* d,
        unsigned a0, unsigned a1, unsigned a2, unsigned a3,
        unsigned b0, unsigned b1) {
    asm volatile(
        "mma.sync.aligned.m16n8k8.row.col.f32.tf32.tf32.f32 "
        "{%0,%1,%2,%3}, {%4,%5,%6,%7}, {%8,%9}, {%0,%1,%2,%3};"
        : "+f"(d[0]), "+f"(d[1]), "+f"(d[2]), "+f"(d[3])
        : "r"(a0), "r"(a1), "r"(a2), "r"(a3), "r"(b0), "r"(b1));
}

__global__ void zero_misc_kernel(float* __restrict__ gf) {
    unsigned i = blockIdx.x * 256u + threadIdx.x;
    if (i < NN) g_cnt[i] = 0;
    if (i < NG * 16u) reinterpret_cast<float4*>(gf)[i] = make_float4(0.f, 0.f, 0.f, 0.f);
    if (i < 256) g_dh[i] = 0;
}

// ---------------- CSR build: hist -> scan -> scatter (int4-vectorized) ----------------
__global__ void hist_kernel(const int4* __restrict__ dst4) {
    unsigned i = blockIdx.x * 256u + threadIdx.x;
    if (i >= NE / 4) return;
    int4 d = __ldcs(&dst4[i]);
    atomicAdd(&g_cnt[d.x], 1);
    atomicAdd(&g_cnt[d.y], 1);
    atomicAdd(&g_cnt[d.z], 1);
    atomicAdd(&g_cnt[d.w], 1);
}

__global__ void scan1_kernel() {
    __shared__ int sm[256];
    int b = blockIdx.x, t = threadIdx.x;
    int base = b * 1024 + t * 4;
    int v[4];
#pragma unroll
    for (int i = 0; i < 4; i++) {
        int idx = base + i;
        v[i] = (idx < NN) ? g_cnt[idx] : 0;
    }
    int s = v[0] + v[1] + v[2] + v[3];
    sm[t] = s;
    __syncthreads();
    for (int d = 1; d < 256; d <<= 1) {
        int x = (t >= d) ? sm[t - d] : 0;
        __syncthreads();
        sm[t] += x;
        __syncthreads();
    }
    int excl = sm[t] - s;
    if (t == 255) g_bsum[b] = sm[255];
    int run = excl;
#pragma unroll
    for (int i = 0; i < 4; i++) {
        int idx = base + i;
        if (idx < NN) g_off[idx] = run;
        run += v[i];
    }
}

__global__ void scan23_kernel() {
    __shared__ int sm[256];
    int b = blockIdx.x, t = threadIdx.x;
    int s = 0;
    for (int i = t; i < b; i += 256) s += g_bsum[i];
    sm[t] = s;
    __syncthreads();
    for (int d = 128; d > 0; d >>= 1) {
        if (t < d) sm[t] += sm[t + d];
        __syncthreads();
    }
    int add = sm[0];
    int base = b * 1024 + t * 4;
#pragma unroll
    for (int i = 0; i < 4; i++) {
        int idx = base + i;
        if (idx < NN) {
            int o = g_off[idx] + add;
            g_off[idx] = o;
            g_cur[idx] = o;
        }
    }
    if (b == NB - 1 && t == 0) g_off[NN] = add + g_bsum[NB - 1];
}

__global__ void scatter_kernel(const int4* __restrict__ src4, const int4* __restrict__ dst4) {
    unsigned i = blockIdx.x * 256u + threadIdx.x;
    if (i >= NE / 4) return;
    unsigned long long pol = mk_pol_last();
    int4 s = __ldcs(&src4[i]);
    int4 d = __ldcs(&dst4[i]);
    int p0 = atomicAdd(&g_cur[d.x], 1);
    st_el_u32(reinterpret_cast<unsigned*>(&g_esrc[p0]), (unsigned)s.x, pol);
    int p1 = atomicAdd(&g_cur[d.y], 1);
    st_el_u32(reinterpret_cast<unsigned*>(&g_esrc[p1]), (unsigned)s.y, pol);
    int p2 = atomicAdd(&g_cur[d.z], 1);
    st_el_u32(reinterpret_cast<unsigned*>(&g_esrc[p2]), (unsigned)s.z, pol);
    int p3 = atomicAdd(&g_cur[d.w], 1);
    st_el_u32(reinterpret_cast<unsigned*>(&g_esrc[p3]), (unsigned)s.w, pol);
}

// ---------------- degree sort: hist -> scan -> block-aggregated scatter ----------------
__global__ void dhist_kernel() {
    __shared__ int h[256];
    int b = blockIdx.x, t = threadIdx.x;
    h[t] = 0;
    __syncthreads();
#pragma unroll
    for (int i = 0; i < 4; i++) {
        int n = b * 1024 + t * 4 + i;
        if (n < NN) {
            int d = min(g_off[n + 1] - g_off[n], 255);
            atomicAdd(&h[d], 1);
        }
    }
    __syncthreads();
    if (h[t] > 0) atomicAdd(&g_dh[t], h[t]);
}

__global__ void dscan_kernel() {    // 1 block, 256 threads: exclusive scan g_dh -> g_dcur
    __shared__ int sm[256];
    int t = threadIdx.x;
    int v = g_dh[t];
    sm[t] = v;
    __syncthreads();
    for (int d = 1; d < 256; d <<= 1) {
        int x = (t >= d) ? sm[t - d] : 0;
        __syncthreads();
        sm[t] += x;
        __syncthreads();
    }
    g_dcur[t] = sm[t] - v;
}

__global__ void dperm_kernel() {
    __shared__ int h[256];
    __shared__ int base[256];
    int b = blockIdx.x, t = threadIdx.x;
    h[t] = 0;
    __syncthreads();
    int dv[4];
#pragma unroll
    for (int i = 0; i < 4; i++) {
        int n = b * 1024 + t * 4 + i;
        dv[i] = -1;
        if (n < NN) {
            dv[i] = min(g_off[n + 1] - g_off[n], 255);
            atomicAdd(&h[dv[i]], 1);
        }
    }
    __syncthreads();
    int cnt = h[t];
    if (cnt > 0) base[t] = atomicAdd(&g_dcur[t], cnt);
    __syncthreads();
    h[t] = 0;
    __syncthreads();
#pragma unroll
    for (int i = 0; i < 4; i++) {
        if (dv[i] >= 0) {
            int n = b * 1024 + t * 4 + i;
            int loc = atomicAdd(&h[dv[i]], 1);
            g_perm[base[dv[i]] + loc] = n;
        }
    }
}

// ---------------- layer-0 GEMM (K padded 74->80), persistent, both W resident ----------------
__global__ void __launch_bounds__(256) gemm_l0(
        const float* __restrict__ hin,
        const float* __restrict__ gW,
        const float* __restrict__ rW,
        const float* __restrict__ rb) {
    constexpr int KP = 80, AST = 84;
    extern __shared__ unsigned dsm[];
    unsigned* Ws0 = dsm;
    unsigned* Ws1 = dsm + KP * 64;
    unsigned* As  = dsm + 2 * KP * 64;

    const int t = threadIdx.x;
    const int lane = t & 31;
    const int wid = t >> 5;
    const int g = lane >> 2;
    const int tig = lane & 3;
    const int wr = wid >> 2;
    const int wc = wid & 3;
    const int r0l = wr * 16 + g;
    const int r1l = r0l + 8;
    unsigned long long pol = mk_pol_last();

    for (int i = t; i < KP * 64; i += 256) {
        int k = i >> 6, c = i & 63;
        int sw = (k << 6) | (c ^ ((k & 3) << 3));
        Ws0[sw] = tf32r((k < INF) ? gW[k * 64 + c] : 0.f);
        Ws1[sw] = tf32r((k < INF) ? rW[k * 64 + c] : 0.f);
    }
    __syncthreads();

    for (int tile = blockIdx.x; tile < NT; tile += GRID_L0) {
        const int rowBase = tile * 32;
        for (int i = t; i < 32 * KP; i += 256) {
            int r = i / KP, k = i - r * KP;
            float v = (k < INF) ? __ldcs(&hin[(size_t)(rowBase + r) * INF + k]) : 0.f;
            As[r * AST + k] = tf32r(v);
        }
        __syncthreads();

        float accP[2][4] = {{0.f,0.f,0.f,0.f},{0.f,0.f,0.f,0.f}};
        float accR[2][4] = {{0.f,0.f,0.f,0.f},{0.f,0.f,0.f,0.f}};
#pragma unroll
        for (int ks = 0; ks < KP / 8; ks++) {
            const int kA = ks * 8 + tig, kB = kA + 4;
            unsigned a0 = As[r0l * AST + kA];
            unsigned a1 = As[r1l * AST + kA];
            unsigned a2 = As[r0l * AST + kB];
            unsigned a3 = As[r1l * AST + kB];
#pragma unroll
            for (int nt = 0; nt < 2; nt++) {
                int n = wc * 16 + nt * 8 + g;
                int swA = (kA << 6) | (n ^ ((kA & 3) << 3));
                int swB = (kB << 6) | (n ^ ((kB & 3) << 3));
                mma_tf32(accP[nt], a0, a1, a2, a3, Ws0[swA], Ws0[swB]);
                mma_tf32(accR[nt], a0, a1, a2, a3, Ws1[swA], Ws1[swB]);
            }
        }
#pragma unroll
        for (int nt = 0; nt < 2; nt++) {
            int col = wc * 16 + nt * 8 + tig * 2;
            size_t o0 = (size_t)(rowBase + r0l) * 64 + col;
            size_t o1 = (size_t)(rowBase + r1l) * 64 + col;
            __half2 p0 = __floats2half2_rn(accP[nt][0], accP[nt][1]);
            __half2 p1 = __floats2half2_rn(accP[nt][2], accP[nt][3]);
            st_el_u32(reinterpret_cast<unsigned*>(&g_Ph[o0]), *reinterpret_cast<unsigned*>(&p0), pol);
            st_el_u32(reinterpret_cast<unsigned*>(&g_Ph[o1]), *reinterpret_cast<unsigned*>(&p1), pol);
            float bx = rb[col], by = rb[col + 1];
            __stcs(reinterpret_cast<float2*>(&g_R[o0]),
                   make_float2(fmaxf(accR[nt][0] + bx, 0.f), fmaxf(accR[nt][1] + by, 0.f)));
            __stcs(reinterpret_cast<float2*>(&g_R[o1]),
                   make_float2(fmaxf(accR[nt][2] + bx, 0.f), fmaxf(accR[nt][3] + by, 0.f)));
        }
        __syncthreads();
    }
}

// ---------------- layers 1/2 GEMM: persistent, prefetch-double-buffered ----------------
__global__ void __launch_bounds__(256) gemm64(
        const float* __restrict__ gW,
        const float* __restrict__ rW,
        const float* __restrict__ rb) {
    constexpr int AST = 68;
    __shared__ unsigned As[32 * AST];
    __shared__ unsigned Ws[64 * 128];

    const int t = threadIdx.x;
    const int lane = t & 31;
    const int wid = t >> 5;
    const int g = lane >> 2;
    const int tig = lane & 3;
    const int wr = wid >> 2;
    const int wc = wid & 3;
    const int r0l = wr * 16 + g;
    const int r1l = r0l + 8;
    unsigned long long pol = mk_pol_last();

    for (int i = t; i < 64 * 128; i += 256) {
        int k = i >> 7, c = i & 127;
        float v = (c < 64) ? gW[k * 64 + c] : rW[k * 64 + (c - 64)];
        Ws[(k << 7) | (c ^ ((k & 3) << 3))] = tf32r(v);
    }

    const int jr0 = t >> 4,          jk0 = t & 15;
    const int jr1 = (t + 256) >> 4,  jk1 = t & 15;

    int tile = blockIdx.x;
    float4 v0, v1;
    if (tile < NT) {
        v0 = __ldcs(reinterpret_cast<const float4*>(&g_H[(size_t)(tile * 32 + jr0) * 64 + jk0 * 4]));
        v1 = __ldcs(reinterpret_cast<const float4*>(&g_H[(size_t)(tile * 32 + jr1) * 64 + jk1 * 4]));
    }
    __syncthreads();

    while (tile < NT) {
        const int rowBase = tile * 32;
        {
            uint4 o;
            o.x = tf32r(v0.x); o.y = tf32r(v0.y); o.z = tf32r(v0.z); o.w = tf32r(v0.w);
            *reinterpret_cast<uint4*>(&As[jr0 * AST + jk0 * 4]) = o;
            o.x = tf32r(v1.x); o.y = tf32r(v1.y); o.z = tf32r(v1.z); o.w = tf32r(v1.w);
            *reinterpret_cast<uint4*>(&As[jr1 * AST + jk1 * 4]) = o;
        }
        __syncthreads();

        const int next = tile + GRID_64;
        if (next < NT) {
            v0 = __ldcs(reinterpret_cast<const float4*>(&g_H[(size_t)(next * 32 + jr0) * 64 + jk0 * 4]));
            v1 = __ldcs(reinterpret_cast<const float4*>(&g_H[(size_t)(next * 32 + jr1) * 64 + jk1 * 4]));
        }

        float acc[4][4];
#pragma unroll
        for (int i = 0; i < 4; i++)
#pragma unroll
            for (int j = 0; j < 4; j++) acc[i][j] = 0.f;

#pragma unroll
        for (int ks = 0; ks < 8; ks++) {
            const int kA = ks * 8 + tig, kB = kA + 4;
            unsigned a0 = As[r0l * AST + kA];
            unsigned a1 = As[r1l * AST + kA];
            unsigned a2 = As[r0l * AST + kB];
            unsigned a3 = As[r1l * AST + kB];
#pragma unroll
            for (int nt = 0; nt < 4; nt++) {
                int n = nt * 32 + wc * 8 + g;
                unsigned b0 = Ws[(kA << 7) | (n ^ ((kA & 3) << 3))];
                unsigned b1 = Ws[(kB << 7) | (n ^ ((kB & 3) << 3))];
                mma_tf32(acc[nt], a0, a1, a2, a3, b0, b1);
            }
        }

#pragma unroll
        for (int nt = 0; nt < 4; nt++) {
            int col = nt * 32 + wc * 8 + tig * 2;
            if (col < 64) {
                size_t o0 = (size_t)(rowBase + r0l) * 64 + col;
                size_t o1 = (size_t)(rowBase + r1l) * 64 + col;
                __half2 p0 = __floats2half2_rn(acc[nt][0], acc[nt][1]);
                __half2 p1 = __floats2half2_rn(acc[nt][2], acc[nt][3]);
                st_el_u32(reinterpret_cast<unsigned*>(&g_Ph[o0]), *reinterpret_cast<unsigned*>(&p0), pol);
                st_el_u32(reinterpret_cast<unsigned*>(&g_Ph[o1]), *reinterpret_cast<unsigned*>(&p1), pol);
            } else {
                int c = col - 64;
                float bx = rb[c], by = rb[c + 1];
                size_t o0 = (size_t)(rowBase + r0l) * 64 + c;
                size_t o1 = (size_t)(rowBase + r1l) * 64 + c;
                __stcs(reinterpret_cast<float2*>(&g_R[o0]),
                       make_float2(fmaxf(acc[nt][0] + bx, 0.f), fmaxf(acc[nt][1] + by, 0.f)));
                __stcs(reinterpret_cast<float2*>(&g_R[o1]),
                       make_float2(fmaxf(acc[nt][2] + bx, 0.f), fmaxf(acc[nt][3] + by, 0.f)));
            }
        }
        __syncthreads();
        tile = next;
    }
}

// ---------------- gather core (half-warp per node, 8-edge batches) ----------------
__device__ __forceinline__ float4 gather_node(int n, int lane, unsigned long long pol) {
    int j = g_off[n];
    const int end = g_off[n + 1];
    const uint2* __restrict__ P2 = reinterpret_cast<const uint2*>(g_Ph);
    float4 acc = make_float4(0.f, 0.f, 0.f, 0.f);
    for (; j + 7 < end; j += 8) {
        int s0 = ld_el_s32(&g_esrc[j], pol);
        int s1 = ld_el_s32(&g_esrc[j + 1], pol);
        int s2 = ld_el_s32(&g_esrc[j + 2], pol);
        int s3 = ld_el_s32(&g_esrc[j + 3], pol);
        int s4 = ld_el_s32(&g_esrc[j + 4], pol);
        int s5 = ld_el_s32(&g_esrc[j + 5], pol);
        int s6 = ld_el_s32(&g_esrc[j + 6], pol);
        int s7 = ld_el_s32(&g_esrc[j + 7], pol);
        uint2 u0 = ld_el_u2(&P2[(size_t)s0 * 16 + lane], pol);
        uint2 u1 = ld_el_u2(&P2[(size_t)s1 * 16 + lane], pol);
        uint2 u2 = ld_el_u2(&P2[(size_t)s2 * 16 + lane], pol);
        uint2 u3 = ld_el_u2(&P2[(size_t)s3 * 16 + lane], pol);
        uint2 u4 = ld_el_u2(&P2[(size_t)s4 * 16 + lane], pol);
        uint2 u5 = ld_el_u2(&P2[(size_t)s5 * 16 + lane], pol);
        uint2 u6 = ld_el_u2(&P2[(size_t)s6 * 16 + lane], pol);
        uint2 u7 = ld_el_u2(&P2[(size_t)s7 * 16 + lane], pol);
#pragma unroll
        for (int q = 0; q < 8; q++) {
            uint2 u = (q == 0) ? u0 : (q == 1) ? u1 : (q == 2) ? u2 : (q == 3) ? u3
                    : (q == 4) ? u4 : (q == 5) ? u5 : (q == 6) ? u6 : u7;
            float2 lo = __half22float2(*reinterpret_cast<const __half2*>(&u.x));
            float2 hi = __half22float2(*reinterpret_cast<const __half2*>(&u.y));
            acc.x += lo.x; acc.y += lo.y; acc.z += hi.x; acc.w += hi.y;
        }
    }
    for (; j < end; j++) {
        int s = ld_el_s32(&g_esrc[j], pol);
        uint2 u = ld_el_u2(&P2[(size_t)s * 16 + lane], pol);
        float2 lo = __half22float2(*reinterpret_cast<const __half2*>(&u.x));
        float2 hi = __half22float2(*reinterpret_cast<const __half2*>(&u.y));
        acc.x += lo.x; acc.y += lo.y; acc.z += hi.x; acc.w += hi.y;
    }
    return acc;
}

__device__ __forceinline__ float4 make_h(float4 acc, float4 b, float4 r) {
    float4 h;
    h.x = fmaxf(acc.x + b.x, 0.f) + r.x;
    h.y = fmaxf(acc.y + b.y, 0.f) + r.y;
    h.z = fmaxf(acc.z + b.z, 0.f) + r.z;
    h.w = fmaxf(acc.w + b.w, 0.f) + r.w;
    return h;
}

// ---------------- agg (degree-sorted half-warp-per-node): writes H ----------------
__global__ void agg_h(const float* __restrict__ gb) {
    unsigned tid = blockIdx.x * 256u + threadIdx.x;
    unsigned idx = tid >> 4;
    if (idx >= NN) return;
    int n = __ldg(&g_perm[idx]);
    int lane = tid & 15;
    unsigned long long pol = mk_pol_last();
    float4 acc = gather_node(n, lane, pol);
    float4 b = *reinterpret_cast<const float4*>(&gb[lane * 4]);
    float4 r = __ldcs(&reinterpret_cast<const float4*>(g_R)[(size_t)n * 16 + lane]);
    __stcs(&reinterpret_cast<float4*>(g_H)[(size_t)n * 16 + lane], make_h(acc, b, r));
}

// ---------------- agg for layer 2 fused with sum-pool ----------------
__global__ void agg_pool(const float* __restrict__ gb, const int* __restrict__ gid) {
    unsigned tid = blockIdx.x * 256u + threadIdx.x;
    unsigned idx = tid >> 4;
    if (idx >= NN) return;
    int n = __ldg(&g_perm[idx]);
    int lane = tid & 15;
    unsigned long long pol = mk_pol_last();
    float4 acc = gather_node(n, lane, pol);
    float4 b = *reinterpret_cast<const float4*>(&gb[lane * 4]);
    float4 r = __ldcs(&reinterpret_cast<const float4*>(g_R)[(size_t)n * 16 + lane]);
    float4 h = make_h(acc, b, r);
    int g = __ldg(&gid[n]);
    red4(&g_GF[(size_t)g * 64 + lane * 4], h);
}

// ---------------- fused classifier MLP ----------------
__global__ void mlp_kernel(const float* __restrict__ cW1, const float* __restrict__ cb1,
                           const float* __restrict__ cW2, const float* __restrict__ cb2,
                           float* __restrict__ out) {
    __shared__ float W1[64 * 128];
    __shared__ float W2[128 * 2];
    __shared__ float Hs[16][128];
    int t = threadIdx.x;
    for (int i = t; i < 64 * 128; i += 256) W1[i] = cW1[i];
    if (t < 256) W2[t] = cW2[t];
    __syncthreads();

    int oc = t & 127;
    int half = t >> 7;
    float bias = __ldg(&cb1[oc]);
#pragma unroll
    for (int i = 0; i < 8; i++) {
        int gi = half * 8 + i;
        int g = blockIdx.x * 16 + gi;
        const float* gf = &g_GF[(size_t)g * 64];
        float s = bias;
#pragma unroll 8
        for (int k = 0; k < 64; k++) s += __ldg(&gf[k]) * W1[k * 128 + oc];
        Hs[gi][oc] = fmaxf(s, 0.f);
    }
    __syncthreads();

    if (t < 32) {
        int gi = t >> 1, cls = t & 1;
        float s = __ldg(&cb2[cls]);
#pragma unroll 8
        for (int k = 0; k < 128; k++) s += Hs[gi][k] * W2[k * 2 + cls];
        out[(blockIdx.x * 16 + gi) * 2 + cls] = s;
    }
}

// ---------------- launch ----------------
extern "C" void kernel_launch(void* const* d_in, const int* in_sizes, int n_in,
                              void* d_out, int out_size) {
    const float* node_feats = (const float*)d_in[0];
    const int*   src        = (const int*)d_in[1];
    const int*   dst        = (const int*)d_in[2];
    const int*   gid        = (const int*)d_in[3];
    const float* gW[3] = {(const float*)d_in[4],  (const float*)d_in[8],  (const float*)d_in[12]};
    const float* gb[3] = {(const float*)d_in[5],  (const float*)d_in[9],  (const float*)d_in[13]};
    const float* rW[3] = {(const float*)d_in[6],  (const float*)d_in[10], (const float*)d_in[14]};
    const float* rb[3] = {(const float*)d_in[7],  (const float*)d_in[11], (const float*)d_in[15]};
    const float* cW1 = (const float*)d_in[16];
    const float* cb1 = (const float*)d_in[17];
    const float* cW2 = (const float*)d_in[18];
    const float* cb2 = (const float*)d_in[19];
    float* out = (float*)d_out;

    float* gfp; cudaGetSymbolAddress((void**)&gfp, g_GF);

    const int E4_BLOCKS  = (NE / 4 + 255) / 256;
    const int ZM_BLOCKS  = (NN + 255) / 256;
    const int DSM_L0     = (2 * 80 * 64 + 32 * 84) * 4;
    const int AGG_BLOCKS = (NN * 16) / 256;       // 31250 (half-warp per node)

    cudaStream_t s2 = g_aux.s;

    // fork: CSR build + degree sort on side stream, layer-0 GEMM on main stream
    cudaEventRecord(g_aux.eFork, 0);
    cudaStreamWaitEvent(s2, g_aux.eFork, 0);

    zero_misc_kernel<<<ZM_BLOCKS, 256, 0, s2>>>(gfp);
    hist_kernel<<<E4_BLOCKS, 256, 0, s2>>>((const int4*)dst);
    scan1_kernel<<<NB, 256, 0, s2>>>();
    scan23_kernel<<<NB, 256, 0, s2>>>();
    scatter_kernel<<<E4_BLOCKS, 256, 0, s2>>>((const int4*)src, (const int4*)dst);
    dhist_kernel<<<NB, 256, 0, s2>>>();
    dscan_kernel<<<1, 256, 0, s2>>>();
    dperm_kernel<<<NB, 256, 0, s2>>>();

    gemm_l0<<<GRID_L0, 256, DSM_L0>>>(node_feats, gW[0], rW[0], rb[0]);

    cudaEventRecord(g_aux.eJoin, s2);
    cudaStreamWaitEvent(0, g_aux.eJoin, 0);

    // ---- strictly sequential layer chain ----
    agg_h<<<AGG_BLOCKS, 256>>>(gb[0]);
    gemm64<<<GRID_64, 256>>>(gW[1], rW[1], rb[1]);
    agg_h<<<AGG_BLOCKS, 256>>>(gb[1]);
    gemm64<<<GRID_64, 256>>>(gW[2], rW[2], rb[2]);
    agg_pool<<<AGG_BLOCKS, 256>>>(gb[2], gid);

    // fused classifier
    mlp_kernel<<<NG / 16, 256>>>(cW1, cb1, cW2, cb2, out);
}

// round 12
// speedup vs baseline: 1.0265x; 1.0265x over previous
#include <cuda_runtime.h>
#include <cuda_fp16.h>
#include <cstdint>

#define NN      500000
#define NE      8000000
#define NG      16384
#define INF     74
#define HID     64
#define CH      128
#define NB      489          // ceil(NN/1024) for the scan
#define NT      (NN / 32)    // 15625 row tiles
#define GRID_L0 592
#define GRID_64 740

// ---------------- scratch (device globals; no allocation) ----------------
__device__ __half g_Ph [(size_t)NN * HID];  // h @ gW, fp16 (L2-pinned)
__device__ float  g_R  [(size_t)NN * HID];  // relu(h @ rW + rb), streaming
__device__ float  g_H  [(size_t)NN * HID];  // layer output H, streaming
__device__ float  g_GF [(size_t)NG * HID];  // pooled graph features

// CSR build scratch
__device__ int g_cnt [NN];
__device__ int g_off [NN + 1];
__device__ int g_cur [NN];
__device__ int g_bsum [512];
__device__ int g_esrc[NE];                  // src ids grouped by dst (L2-pinned)

// ---------------- side stream + events + smem opt-in (once; no device mem) ----------------
__global__ void __launch_bounds__(256) gemm_l0(const float*, const float*, const float*, const float*);
struct AuxRes {
    cudaStream_t s;
    cudaEvent_t eFork, eJoin;
    AuxRes() {
        cudaStreamCreate(&s);
        cudaEventCreateWithFlags(&eFork, cudaEventDisableTiming);
        cudaEventCreateWithFlags(&eJoin, cudaEventDisableTiming);
        cudaFuncSetAttribute(gemm_l0, cudaFuncAttributeMaxDynamicSharedMemorySize, 56 * 1024);
    }
};
static AuxRes g_aux;

// ---------------- helpers ----------------
__device__ __forceinline__ void red4(float* p, float4 v) {
    asm volatile("red.global.add.v4.f32 [%0], {%1,%2,%3,%4};"
                 :: "l"(p), "f"(v.x), "f"(v.y), "f"(v.z), "f"(v.w)
                 : "memory");
}

__device__ __forceinline__ unsigned long long mk_pol_last() {
    unsigned long long p;
    asm("createpolicy.fractional.L2::evict_last.b64 %0, 1.0;" : "=l"(p));
    return p;
}
__device__ __forceinline__ uint2 ld_el_u2(const uint2* a, unsigned long long pol) {
    uint2 r;
    asm("ld.global.nc.L2::cache_hint.v2.u32 {%0,%1}, [%2], %3;"
        : "=r"(r.x), "=r"(r.y) : "l"(a), "l"(pol));
    return r;
}
__device__ __forceinline__ int ld_el_s32(const int* a, unsigned long long pol) {
    int r;
    asm("ld.global.nc.L2::cache_hint.b32 %0, [%1], %2;" : "=r"(r) : "l"(a), "l"(pol));
    return r;
}
__device__ __forceinline__ void st_el_u32(unsigned* a, unsigned v, unsigned long long pol) {
    asm volatile("st.global.L2::cache_hint.b32 [%0], %1, %2;" :: "l"(a), "r"(v), "l"(pol) : "memory");
}

__device__ __forceinline__ unsigned tf32r(float x) {
    unsigned u;
    asm("cvt.rna.tf32.f32 %0, %1;" : "=r"(u) : "f"(x));
    return u;
}

__device__ __forceinline__ void mma_tf32(float* d,
        unsigned a0, unsigned a1, unsigned a2, unsigned a3,
        unsigned b0, unsigned b1) {
    asm volatile(
        "mma.sync.aligned.m16n8k8.row.col.f32.tf32.tf32.f32 "
        "{%0,%1,%2,%3}, {%4,%5,%6,%7}, {%8,%9}, {%0,%1,%2,%3};"
        : "+f"(d[0]), "+f"(d[1]), "+f"(d[2]), "+f"(d[3])
        : "r"(a0), "r"(a1), "r"(a2), "r"(a3), "r"(b0), "r"(b1));
}

__global__ void zero_misc_kernel(float* __restrict__ gf) {
    unsigned i = blockIdx.x * 256u + threadIdx.x;
    if (i < NN) g_cnt[i] = 0;
    if (i < NG * 16u) reinterpret_cast<float4*>(gf)[i] = make_float4(0.f, 0.f, 0.f, 0.f);
}

// ---------------- CSR build: hist -> scan -> scatter (int4-vectorized) ----------------
__global__ void hist_kernel(const int4* __restrict__ dst4) {
    unsigned i = blockIdx.x * 256u + threadIdx.x;
    if (i >= NE / 4) return;
    int4 d = __ldcs(&dst4[i]);
    atomicAdd(&g_cnt[d.x], 1);
    atomicAdd(&g_cnt[d.y], 1);
    atomicAdd(&g_cnt[d.z], 1);
    atomicAdd(&g_cnt[d.w], 1);
}

__global__ void scan1_kernel() {
    __shared__ int sm[256];
    int b = blockIdx.x, t = threadIdx.x;
    int base = b * 1024 + t * 4;
    int v[4];
#pragma unroll
    for (int i = 0; i < 4; i++) {
        int idx = base + i;
        v[i] = (idx < NN) ? g_cnt[idx] : 0;
    }
    int s = v[0] + v[1] + v[2] + v[3];
    sm[t] = s;
    __syncthreads();
    for (int d = 1; d < 256; d <<= 1) {
        int x = (t >= d) ? sm[t - d] : 0;
        __syncthreads();
        sm[t] += x;
        __syncthreads();
    }
    int excl = sm[t] - s;
    if (t == 255) g_bsum[b] = sm[255];
    int run = excl;
#pragma unroll
    for (int i = 0; i < 4; i++) {
        int idx = base + i;
        if (idx < NN) g_off[idx] = run;
        run += v[i];
    }
}

__global__ void scan23_kernel() {
    __shared__ int sm[256];
    int b = blockIdx.x, t = threadIdx.x;
    int s = 0;
    for (int i = t; i < b; i += 256) s += g_bsum[i];
    sm[t] = s;
    __syncthreads();
    for (int d = 128; d > 0; d >>= 1) {
        if (t < d) sm[t] += sm[t + d];
        __syncthreads();
    }
    int add = sm[0];
    int base = b * 1024 + t * 4;
#pragma unroll
    for (int i = 0; i < 4; i++) {
        int idx = base + i;
        if (idx < NN) {
            int o = g_off[idx] + add;
            g_off[idx] = o;
            g_cur[idx] = o;
        }
    }
    if (b == NB - 1 && t == 0) g_off[NN] = add + g_bsum[NB - 1];
}

__global__ void scatter_kernel(const int4* __restrict__ src4, const int4* __restrict__ dst4) {
    unsigned i = blockIdx.x * 256u + threadIdx.x;
    if (i >= NE / 4) return;
    unsigned long long pol = mk_pol_last();
    int4 s = __ldcs(&src4[i]);
    int4 d = __ldcs(&dst4[i]);
    int p0 = atomicAdd(&g_cur[d.x], 1);
    st_el_u32(reinterpret_cast<unsigned*>(&g_esrc[p0]), (unsigned)s.x, pol);
    int p1 = atomicAdd(&g_cur[d.y], 1);
    st_el_u32(reinterpret_cast<unsigned*>(&g_esrc[p1]), (unsigned)s.y, pol);
    int p2 = atomicAdd(&g_cur[d.z], 1);
    st_el_u32(reinterpret_cast<unsigned*>(&g_esrc[p2]), (unsigned)s.z, pol);
    int p3 = atomicAdd(&g_cur[d.w], 1);
    st_el_u32(reinterpret_cast<unsigned*>(&g_esrc[p3]), (unsigned)s.w, pol);
}

// ---------------- layer-0 GEMM (K padded 74->80), persistent, both W resident ----------------
__global__ void __launch_bounds__(256) gemm_l0(
        const float* __restrict__ hin,
        const float* __restrict__ gW,
        const float* __restrict__ rW,
        const float* __restrict__ rb) {
    constexpr int KP = 80, AST = 84;
    extern __shared__ unsigned dsm[];
    unsigned* Ws0 = dsm;
    unsigned* Ws1 = dsm + KP * 64;
    unsigned* As  = dsm + 2 * KP * 64;

    const int t = threadIdx.x;
    const int lane = t & 31;
    const int wid = t >> 5;
    const int g = lane >> 2;
    const int tig = lane & 3;
    const int wr = wid >> 2;
    const int wc = wid & 3;
    const int r0l = wr * 16 + g;
    const int r1l = r0l + 8;
    unsigned long long pol = mk_pol_last();

    for (int i = t; i < KP * 64; i += 256) {
        int k = i >> 6, c = i & 63;
        int sw = (k << 6) | (c ^ ((k & 3) << 3));
        Ws0[sw] = tf32r((k < INF) ? gW[k * 64 + c] : 0.f);
        Ws1[sw] = tf32r((k < INF) ? rW[k * 64 + c] : 0.f);
    }
    __syncthreads();

    for (int tile = blockIdx.x; tile < NT; tile += GRID_L0) {
        const int rowBase = tile * 32;
        for (int i = t; i < 32 * KP; i += 256) {
            int r = i / KP, k = i - r * KP;
            float v = (k < INF) ? __ldcs(&hin[(size_t)(rowBase + r) * INF + k]) : 0.f;
            As[r * AST + k] = tf32r(v);
        }
        __syncthreads();

        float accP[2][4] = {{0.f,0.f,0.f,0.f},{0.f,0.f,0.f,0.f}};
        float accR[2][4] = {{0.f,0.f,0.f,0.f},{0.f,0.f,0.f,0.f}};
#pragma unroll
        for (int ks = 0; ks < KP / 8; ks++) {
            const int kA = ks * 8 + tig, kB = kA + 4;
            unsigned a0 = As[r0l * AST + kA];
            unsigned a1 = As[r1l * AST + kA];
            unsigned a2 = As[r0l * AST + kB];
            unsigned a3 = As[r1l * AST + kB];
#pragma unroll
            for (int nt = 0; nt < 2; nt++) {
                int n = wc * 16 + nt * 8 + g;
                int swA = (kA << 6) | (n ^ ((kA & 3) << 3));
                int swB = (kB << 6) | (n ^ ((kB & 3) << 3));
                mma_tf32(accP[nt], a0, a1, a2, a3, Ws0[swA], Ws0[swB]);
                mma_tf32(accR[nt], a0, a1, a2, a3, Ws1[swA], Ws1[swB]);
            }
        }
#pragma unroll
        for (int nt = 0; nt < 2; nt++) {
            int col = wc * 16 + nt * 8 + tig * 2;
            size_t o0 = (size_t)(rowBase + r0l) * 64 + col;
            size_t o1 = (size_t)(rowBase + r1l) * 64 + col;
            __half2 p0 = __floats2half2_rn(accP[nt][0], accP[nt][1]);
            __half2 p1 = __floats2half2_rn(accP[nt][2], accP[nt][3]);
            st_el_u32(reinterpret_cast<unsigned*>(&g_Ph[o0]), *reinterpret_cast<unsigned*>(&p0), pol);
            st_el_u32(reinterpret_cast<unsigned*>(&g_Ph[o1]), *reinterpret_cast<unsigned*>(&p1), pol);
            float bx = rb[col], by = rb[col + 1];
            __stcs(reinterpret_cast<float2*>(&g_R[o0]),
                   make_float2(fmaxf(accR[nt][0] + bx, 0.f), fmaxf(accR[nt][1] + by, 0.f)));
            __stcs(reinterpret_cast<float2*>(&g_R[o1]),
                   make_float2(fmaxf(accR[nt][2] + bx, 0.f), fmaxf(accR[nt][3] + by, 0.f)));
        }
        __syncthreads();
    }
}

// ---------------- layers 1/2 GEMM: persistent, prefetch-double-buffered ----------------
__global__ void __launch_bounds__(256) gemm64(
        const float* __restrict__ gW,
        const float* __restrict__ rW,
        const float* __restrict__ rb) {
    constexpr int AST = 68;
    __shared__ unsigned As[32 * AST];
    __shared__ unsigned Ws[64 * 128];

    const int t = threadIdx.x;
    const int lane = t & 31;
    const int wid = t >> 5;
    const int g = lane >> 2;
    const int tig = lane & 3;
    const int wr = wid >> 2;
    const int wc = wid & 3;
    const int r0l = wr * 16 + g;
    const int r1l = r0l + 8;
    unsigned long long pol = mk_pol_last();

    for (int i = t; i < 64 * 128; i += 256) {
        int k = i >> 7, c = i & 127;
        float v = (c < 64) ? gW[k * 64 + c] : rW[k * 64 + (c - 64)];
        Ws[(k << 7) | (c ^ ((k & 3) << 3))] = tf32r(v);
    }

    const int jr0 = t >> 4,          jk0 = t & 15;
    const int jr1 = (t + 256) >> 4,  jk1 = t & 15;

    int tile = blockIdx.x;
    float4 v0, v1;
    if (tile < NT) {
        v0 = __ldcs(reinterpret_cast<const float4*>(&g_H[(size_t)(tile * 32 + jr0) * 64 + jk0 * 4]));
        v1 = __ldcs(reinterpret_cast<const float4*>(&g_H[(size_t)(tile * 32 + jr1) * 64 + jk1 * 4]));
    }
    __syncthreads();

    while (tile < NT) {
        const int rowBase = tile * 32;
        {
            uint4 o;
            o.x = tf32r(v0.x); o.y = tf32r(v0.y); o.z = tf32r(v0.z); o.w = tf32r(v0.w);
            *reinterpret_cast<uint4*>(&As[jr0 * AST + jk0 * 4]) = o;
            o.x = tf32r(v1.x); o.y = tf32r(v1.y); o.z = tf32r(v1.z); o.w = tf32r(v1.w);
            *reinterpret_cast<uint4*>(&As[jr1 * AST + jk1 * 4]) = o;
        }
        __syncthreads();

        const int next = tile + GRID_64;
        if (next < NT) {
            v0 = __ldcs(reinterpret_cast<const float4*>(&g_H[(size_t)(next * 32 + jr0) * 64 + jk0 * 4]));
            v1 = __ldcs(reinterpret_cast<const float4*>(&g_H[(size_t)(next * 32 + jr1) * 64 + jk1 * 4]));
        }

        float acc[4][4];
#pragma unroll
        for (int i = 0; i < 4; i++)
#pragma unroll
            for (int j = 0; j < 4; j++) acc[i][j] = 0.f;

#pragma unroll
        for (int ks = 0; ks < 8; ks++) {
            const int kA = ks * 8 + tig, kB = kA + 4;
            unsigned a0 = As[r0l * AST + kA];
            unsigned a1 = As[r1l * AST + kA];
            unsigned a2 = As[r0l * AST + kB];
            unsigned a3 = As[r1l * AST + kB];
#pragma unroll
            for (int nt = 0; nt < 4; nt++) {
                int n = nt * 32 + wc * 8 + g;
                unsigned b0 = Ws[(kA << 7) | (n ^ ((kA & 3) << 3))];
                unsigned b1 = Ws[(kB << 7) | (n ^ ((kB & 3) << 3))];
                mma_tf32(acc[nt], a0, a1, a2, a3, b0, b1);
            }
        }

#pragma unroll
        for (int nt = 0; nt < 4; nt++) {
            int col = nt * 32 + wc * 8 + tig * 2;
            if (col < 64) {
                size_t o0 = (size_t)(rowBase + r0l) * 64 + col;
                size_t o1 = (size_t)(rowBase + r1l) * 64 + col;
                __half2 p0 = __floats2half2_rn(acc[nt][0], acc[nt][1]);
                __half2 p1 = __floats2half2_rn(acc[nt][2], acc[nt][3]);
                st_el_u32(reinterpret_cast<unsigned*>(&g_Ph[o0]), *reinterpret_cast<unsigned*>(&p0), pol);
                st_el_u32(reinterpret_cast<unsigned*>(&g_Ph[o1]), *reinterpret_cast<unsigned*>(&p1), pol);
            } else {
                int c = col - 64;
                float bx = rb[c], by = rb[c + 1];
                size_t o0 = (size_t)(rowBase + r0l) * 64 + c;
                size_t o1 = (size_t)(rowBase + r1l) * 64 + c;
                __stcs(reinterpret_cast<float2*>(&g_R[o0]),
                       make_float2(fmaxf(acc[nt][0] + bx, 0.f), fmaxf(acc[nt][1] + by, 0.f)));
                __stcs(reinterpret_cast<float2*>(&g_R[o1]),
                       make_float2(fmaxf(acc[nt][2] + bx, 0.f), fmaxf(acc[nt][3] + by, 0.f)));
            }
        }
        __syncthreads();
        tile = next;
    }
}

// ---------------- gather core: index loads via 1 LDG + shfl broadcast ----------------
// half-warp (16 lanes) per node, uint2 (4 halves) per lane; edge order preserved.
// hm = this half-warp's 16-lane mask; all 16 lanes execute the loop in lockstep.
__device__ __forceinline__ float4 gather_node(int n, int lane, unsigned hm,
                                              unsigned long long pol) {
    int j = g_off[n];
    const int end = g_off[n + 1];
    const uint2* __restrict__ P2 = reinterpret_cast<const uint2*>(g_Ph);
    float4 acc = make_float4(0.f, 0.f, 0.f, 0.f);
    for (; j + 7 < end; j += 8) {
        int my = 0;
        if (lane < 8) my = ld_el_s32(&g_esrc[j + lane], pol);
        int s0 = __shfl_sync(hm, my, 0, 16);
        int s1 = __shfl_sync(hm, my, 1, 16);
        int s2 = __shfl_sync(hm, my, 2, 16);
        int s3 = __shfl_sync(hm, my, 3, 16);
        int s4 = __shfl_sync(hm, my, 4, 16);
        int s5 = __shfl_sync(hm, my, 5, 16);
        int s6 = __shfl_sync(hm, my, 6, 16);
        int s7 = __shfl_sync(hm, my, 7, 16);
        uint2 u0 = ld_el_u2(&P2[(size_t)s0 * 16 + lane], pol);
        uint2 u1 = ld_el_u2(&P2[(size_t)s1 * 16 + lane], pol);
        uint2 u2 = ld_el_u2(&P2[(size_t)s2 * 16 + lane], pol);
        uint2 u3 = ld_el_u2(&P2[(size_t)s3 * 16 + lane], pol);
        uint2 u4 = ld_el_u2(&P2[(size_t)s4 * 16 + lane], pol);
        uint2 u5 = ld_el_u2(&P2[(size_t)s5 * 16 + lane], pol);
        uint2 u6 = ld_el_u2(&P2[(size_t)s6 * 16 + lane], pol);
        uint2 u7 = ld_el_u2(&P2[(size_t)s7 * 16 + lane], pol);
#pragma unroll
        for (int q = 0; q < 8; q++) {
            uint2 u = (q == 0) ? u0 : (q == 1) ? u1 : (q == 2) ? u2 : (q == 3) ? u3
                    : (q == 4) ? u4 : (q == 5) ? u5 : (q == 6) ? u6 : u7;
            float2 lo = __half22float2(*reinterpret_cast<const __half2*>(&u.x));
            float2 hi = __half22float2(*reinterpret_cast<const __half2*>(&u.y));
            acc.x += lo.x; acc.y += lo.y; acc.z += hi.x; acc.w += hi.y;
        }
    }
    for (; j < end; j++) {
        int s = ld_el_s32(&g_esrc[j], pol);
        uint2 u = ld_el_u2(&P2[(size_t)s * 16 + lane], pol);
        float2 lo = __half22float2(*reinterpret_cast<const __half2*>(&u.x));
        float2 hi = __half22float2(*reinterpret_cast<const __half2*>(&u.y));
        acc.x += lo.x; acc.y += lo.y; acc.z += hi.x; acc.w += hi.y;
    }
    return acc;
}

__device__ __forceinline__ float4 make_h(float4 acc, float4 b, float4 r) {
    float4 h;
    h.x = fmaxf(acc.x + b.x, 0.f) + r.x;
    h.y = fmaxf(acc.y + b.y, 0.f) + r.y;
    h.z = fmaxf(acc.z + b.z, 0.f) + r.z;
    h.w = fmaxf(acc.w + b.w, 0.f) + r.w;
    return h;
}

// ---------------- agg (half-warp-per-node): writes H = relu(acc+gb)+R ----------------
__global__ void agg_h(const float* __restrict__ gb) {
    unsigned tid = blockIdx.x * 256u + threadIdx.x;
    unsigned n = tid >> 4;
    if (n >= NN) return;
    int lane = tid & 15;
    unsigned hm = 0xffffu << (threadIdx.x & 16);
    unsigned long long pol = mk_pol_last();
    float4 acc = gather_node(n, lane, hm, pol);
    float4 b = *reinterpret_cast<const float4*>(&gb[lane * 4]);
    float4 r = __ldcs(&reinterpret_cast<const float4*>(g_R)[(size_t)n * 16 + lane]);
    __stcs(&reinterpret_cast<float4*>(g_H)[(size_t)n * 16 + lane], make_h(acc, b, r));
}

// ---------------- agg for layer 2 fused with sum-pool ----------------
__global__ void agg_pool(const float* __restrict__ gb, const int* __restrict__ gid) {
    unsigned tid = blockIdx.x * 256u + threadIdx.x;
    unsigned n = tid >> 4;
    if (n >= NN) return;
    int lane = tid & 15;
    unsigned hm = 0xffffu << (threadIdx.x & 16);
    unsigned long long pol = mk_pol_last();
    float4 acc = gather_node(n, lane, hm, pol);
    float4 b = *reinterpret_cast<const float4*>(&gb[lane * 4]);
    float4 r = __ldcs(&reinterpret_cast<const float4*>(g_R)[(size_t)n * 16 + lane]);
    float4 h = make_h(acc, b, r);
    int g = __ldg(&gid[n]);
    red4(&g_GF[(size_t)g * 64 + lane * 4], h);
}

// ---------------- fused classifier MLP ----------------
__global__ void mlp_kernel(const float* __restrict__ cW1, const float* __restrict__ cb1,
                           const float* __restrict__ cW2, const float* __restrict__ cb2,
                           float* __restrict__ out) {
    __shared__ float W1[64 * 128];
    __shared__ float W2[128 * 2];
    __shared__ float Hs[16][128];
    int t = threadIdx.x;
    for (int i = t; i < 64 * 128; i += 256) W1[i] = cW1[i];
    if (t < 256) W2[t] = cW2[t];
    __syncthreads();

    int oc = t & 127;
    int half = t >> 7;
    float bias = __ldg(&cb1[oc]);
#pragma unroll
    for (int i = 0; i < 8; i++) {
        int gi = half * 8 + i;
        int g = blockIdx.x * 16 + gi;
        const float* gf = &g_GF[(size_t)g * 64];
        float s = bias;
#pragma unroll 8
        for (int k = 0; k < 64; k++) s += __ldg(&gf[k]) * W1[k * 128 + oc];
        Hs[gi][oc] = fmaxf(s, 0.f);
    }
    __syncthreads();

    if (t < 32) {
        int gi = t >> 1, cls = t & 1;
        float s = __ldg(&cb2[cls]);
#pragma unroll 8
        for (int k = 0; k < 128; k++) s += Hs[gi][k] * W2[k * 2 + cls];
        out[(blockIdx.x * 16 + gi) * 2 + cls] = s;
    }
}

// ---------------- launch ----------------
extern "C" void kernel_launch(void* const* d_in, const int* in_sizes, int n_in,
                              void* d_out, int out_size) {
    const float* node_feats = (const float*)d_in[0];
    const int*   src        = (const int*)d_in[1];
    const int*   dst        = (const int*)d_in[2];
    const int*   gid        = (const int*)d_in[3];
    const float* gW[3] = {(const float*)d_in[4],  (const float*)d_in[8],  (const float*)d_in[12]};
    const float* gb[3] = {(const float*)d_in[5],  (const float*)d_in[9],  (const float*)d_in[13]};
    const float* rW[3] = {(const float*)d_in[6],  (const float*)d_in[10], (const float*)d_in[14]};
    const float* rb[3] = {(const float*)d_in[7],  (const float*)d_in[11], (const float*)d_in[15]};
    const float* cW1 = (const float*)d_in[16];
    const float* cb1 = (const float*)d_in[17];
    const float* cW2 = (const float*)d_in[18];
    const float* cb2 = (const float*)d_in[19];
    float* out = (float*)d_out;

    float* gfp; cudaGetSymbolAddress((void**)&gfp, g_GF);

    const int E4_BLOCKS  = (NE / 4 + 255) / 256;
    const int ZM_BLOCKS  = (NN + 255) / 256;
    const int DSM_L0     = (2 * 80 * 64 + 32 * 84) * 4;
    const int AGG_BLOCKS = (NN * 16) / 256;       // 31250 (half-warp per node)

    cudaStream_t s2 = g_aux.s;

    // fork: CSR build on side stream, layer-0 GEMM on main stream
    cudaEventRecord(g_aux.eFork, 0);
    cudaStreamWaitEvent(s2, g_aux.eFork, 0);

    zero_misc_kernel<<<ZM_BLOCKS, 256, 0, s2>>>(gfp);
    hist_kernel<<<E4_BLOCKS, 256, 0, s2>>>((const int4*)dst);
    scan1_kernel<<<NB, 256, 0, s2>>>();
    scan23_kernel<<<NB, 256, 0, s2>>>();
    scatter_kernel<<<E4_BLOCKS, 256, 0, s2>>>((const int4*)src, (const int4*)dst);

    gemm_l0<<<GRID_L0, 256, DSM_L0>>>(node_feats, gW[0], rW[0], rb[0]);

    cudaEventRecord(g_aux.eJoin, s2);
    cudaStreamWaitEvent(0, g_aux.eJoin, 0);

    // ---- strictly sequential layer chain ----
    agg_h<<<AGG_BLOCKS, 256>>>(gb[0]);
    gemm64<<<GRID_64, 256>>>(gW[1], rW[1], rb[1]);
    agg_h<<<AGG_BLOCKS, 256>>>(gb[1]);
    gemm64<<<GRID_64, 256>>>(gW[2], rW[2], rb[2]);
    agg_pool<<<AGG_BLOCKS, 256>>>(gb[2], gid);

    // fused classifier
    mlp_kernel<<<NG / 16, 256>>>(cW1, cb1, cW2, cb2, out);
}